// round 5
// baseline (speedup 1.0000x reference)
#include <cuda_runtime.h>
#include <cuda_bf16.h>
#include <cstdint>
#include <math.h>

#define D 768
#define B 512
#define NTOT (2 * D)            // 1536 rows of concatenated W

// GEMM tiling: CTA 128x256, 512 threads, warp tile 64x32 (2 x 8 warp grid)
#define TM 128
#define TN 256
#define TK 64                   // bf16 per chunk (128 B = one swizzled row)
#define STAGES 3
#define KHALF 384
#define CHUNKS_PER (KHALF / TK) // 6
#define NCTA 144                // (6, 4, 6)
#define NTHREADS 512

#define A_TILE_BYTES 16384      // 128 x 128B
#define B_TILE_BYTES 32768      // 256 x 128B
#define STAGE_BYTES (A_TILE_BYTES + B_TILE_BYTES)
#define SMEM_TILES_OFF 1024
#define SMEM_TOTAL (SMEM_TILES_OFF + STAGES * STAGE_BYTES)   // 148480

// ---------------------------------------------------------------------------
// Device scratch (allocation-free)
// ---------------------------------------------------------------------------
__device__ __nv_bfloat16 g_s_hi[B * D];
__device__ __nv_bfloat16 g_s_lo[B * D];
__device__ __nv_bfloat16 g_W_hi[NTOT * D];
__device__ __nv_bfloat16 g_W_lo[NTOT * D];
__device__ float g_logits[B * 2];
__device__ int   g_sync;

// ---------------------------------------------------------------------------
// PTX helpers (sm_80-era: legal on the plain sm_103 target)
// ---------------------------------------------------------------------------
__device__ __forceinline__ uint32_t smem_u32(const void* p) {
    uint32_t a;
    asm("{ .reg .u64 t; cvta.to.shared.u64 t, %1; cvt.u32.u64 %0, t; }"
        : "=r"(a) : "l"(p));
    return a;
}

#define SWZ(o) ((o) ^ (((o) >> 3) & 0x70))

__device__ __forceinline__ void cp_async16(uint32_t dst, const void* src) {
    asm volatile("cp.async.cg.shared.global [%0], [%1], 16;"
                 :: "r"(dst), "l"(src));
}
#define CP_COMMIT() asm volatile("cp.async.commit_group;" ::: "memory")
#define CP_WAIT(n)  asm volatile("cp.async.wait_group %0;" :: "n"(n) : "memory")

#define LDSM_X4(r, addr) \
    asm volatile("ldmatrix.sync.aligned.m8n8.x4.shared.b16 {%0,%1,%2,%3}, [%4];" \
                 : "=r"((r)[0]), "=r"((r)[1]), "=r"((r)[2]), "=r"((r)[3]) \
                 : "r"(addr))

#define MMA_BF16(d, a, b0, b1) \
    asm volatile("mma.sync.aligned.m16n8k16.row.col.f32.bf16.bf16.f32 " \
                 "{%0,%1,%2,%3}, {%4,%5,%6,%7}, {%8,%9}, {%0,%1,%2,%3};" \
                 : "+f"((d)[0]), "+f"((d)[1]), "+f"((d)[2]), "+f"((d)[3]) \
                 : "r"((a)[0]), "r"((a)[1]), "r"((a)[2]), "r"((a)[3]), \
                   "r"(b0), "r"(b1))

// ---------------------------------------------------------------------------
// Kernel 1: split fp32 -> bf16 hi/lo; 8 floats/thread, 128-bit stores.
// Also: logits = bias, g_sync = 0.
// ---------------------------------------------------------------------------
__global__ __launch_bounds__(256)
void split_kernel(const float4* __restrict__ W4p,
                  const float4* __restrict__ S4p,
                  const float* __restrict__ fc_b) {
    const int WP = NTOT * D / 8;   // 147456
    const int SP = B * D / 8;      // 49152
    int g = blockIdx.x * blockDim.x + threadIdx.x;

    if (g == 0) g_sync = 0;
    if (g < B * 2) g_logits[g] = fc_b[g & 1];
    if (g >= WP + SP) return;

    float4 x0, x1;
    __nv_bfloat16 *hi, *lo;
    int e;
    if (g < WP) { x0 = W4p[2 * g]; x1 = W4p[2 * g + 1]; hi = g_W_hi; lo = g_W_lo; e = g * 8; }
    else {
        int q = g - WP;
        x0 = S4p[2 * q]; x1 = S4p[2 * q + 1]; hi = g_s_hi; lo = g_s_lo; e = q * 8;
    }

    float v[8] = {x0.x, x0.y, x0.z, x0.w, x1.x, x1.y, x1.z, x1.w};
    uint32_t H[4], L[4];
#pragma unroll
    for (int j = 0; j < 4; j++) {
        float a = v[2 * j], bq = v[2 * j + 1];
        __nv_bfloat162 h2 = __floats2bfloat162_rn(a, bq);
        float ra = a  - __bfloat162float(__low2bfloat16(h2));
        float rb = bq - __bfloat162float(__high2bfloat16(h2));
        __nv_bfloat162 l2 = __floats2bfloat162_rn(ra, rb);
        H[j] = *(uint32_t*)&h2;
        L[j] = *(uint32_t*)&l2;
    }
    *(uint4*)(hi + e) = make_uint4(H[0], H[1], H[2], H[3]);
    *(uint4*)(lo + e) = make_uint4(L[0], L[1], L[2], L[3]);
}

// ---------------------------------------------------------------------------
// Stage loader (512 threads): A tile 128x64 (16 KB, 2 rounds) +
// B tile 256x64 (32 KB, 4 rounds), SW128 swizzle, one commit_group.
// ---------------------------------------------------------------------------
__device__ __forceinline__ void load_stage(uint32_t sA, uint32_t sB,
                                           const __nv_bfloat16* Asrc,
                                           const __nv_bfloat16* Bsrc,
                                           int rowBase, int colBase, int kOff,
                                           int tid) {
#pragma unroll
    for (int r = 0; r < 2; r++) {
        int c = tid + r * NTHREADS;
        int row = c >> 3, col = c & 7;
        uint32_t off = SWZ(row * 128 + col * 16);
        cp_async16(sA + off, Asrc + (size_t)(rowBase + row) * D + kOff + col * 8);
    }
#pragma unroll
    for (int r = 0; r < 4; r++) {
        int c = tid + r * NTHREADS;
        int row = c >> 3, col = c & 7;
        uint32_t off = SWZ(row * 128 + col * 16);
        cp_async16(sB + off, Bsrc + (size_t)(colBase + row) * D + kOff + col * 8);
    }
    CP_COMMIT();
}

// ---------------------------------------------------------------------------
// Kernel 2: HMMA GEMM (warp tile 64x32, 16 warps) + v-dot reduce +
// device-wide barrier + softmax/fuse. Grid (6, 4, 6) = 144 CTAs, 512 thr.
// z: seg = z>>1 (hi*hi / hi*lo / lo*hi), khalf = z&1.
// ---------------------------------------------------------------------------
__global__ __launch_bounds__(NTHREADS, 1)
void gemm_fuse_kernel(const float* __restrict__ V,
                      const float* __restrict__ S,
                      float* __restrict__ out) {
    extern __shared__ char smem[];
    const uint32_t smem_base = smem_u32(smem);
    float* rowAcc = (float*)smem;               // 128 floats, below tile area

    const int tid  = threadIdx.x;
    const int wid  = tid >> 5;
    const int lane = tid & 31;
    const int warp_m = wid & 1;                 // 2 x 64 rows
    const int warp_n = wid >> 1;                // 8 x 32 cols

    const int colBase = blockIdx.x * TN;        // 0..1280 within Wcat
    const int rowBase = blockIdx.y * TM;        // 0..384
    const int seg     = blockIdx.z >> 1;        // 0: hi*hi, 1: hi*lo, 2: lo*hi
    const int kOff0   = (blockIdx.z & 1) * KHALF;
    const __nv_bfloat16* Asrc = (seg < 2) ? g_s_hi : g_s_lo;
    const __nv_bfloat16* Bsrc = (seg == 1) ? g_W_lo : g_W_hi;

    if (tid < TM) rowAcc[tid] = 0.0f;

#pragma unroll
    for (int p = 0; p < STAGES - 1; p++) {
        uint32_t sA = smem_base + SMEM_TILES_OFF + p * STAGE_BYTES;
        load_stage(sA, sA + A_TILE_BYTES, Asrc, Bsrc, rowBase, colBase,
                   kOff0 + p * TK, tid);
    }

    float acc[4][4][4] = {};                    // [m16 tile][n8 tile][frag]

    const int rowA = lane & 15, colSelA = lane >> 4;
    const int rowB = ((lane >> 4) << 3) + (lane & 7), colSelB = (lane >> 3) & 1;

    for (int it = 0; it < CHUNKS_PER; it++) {
        if (it < CHUNKS_PER - 1) CP_WAIT(1);
        else                     CP_WAIT(0);
        __syncthreads();

        int nx = it + STAGES - 1;
        if (nx < CHUNKS_PER) {
            uint32_t nA = smem_base + SMEM_TILES_OFF + (nx % STAGES) * STAGE_BYTES;
            load_stage(nA, nA + A_TILE_BYTES, Asrc, Bsrc, rowBase, colBase,
                       kOff0 + nx * TK, tid);
        }

        const uint32_t sA = smem_base + SMEM_TILES_OFF + (it % STAGES) * STAGE_BYTES;
        const uint32_t sB = sA + A_TILE_BYTES;

#pragma unroll
        for (int ks = 0; ks < 4; ks++) {
            uint32_t a[4][4];
            uint32_t b[2][4];
#pragma unroll
            for (int mi = 0; mi < 4; mi++) {
                uint32_t addr = sA + SWZ((64 * warp_m + 16 * mi + rowA) * 128
                                         + (2 * ks + colSelA) * 16);
                LDSM_X4(a[mi], addr);
            }
#pragma unroll
            for (int q = 0; q < 2; q++) {
                uint32_t addr = sB + SWZ((32 * warp_n + 16 * q + rowB) * 128
                                         + (2 * ks + colSelB) * 16);
                LDSM_X4(b[q], addr);
            }
#pragma unroll
            for (int mi = 0; mi < 4; mi++)
#pragma unroll
                for (int nj = 0; nj < 4; nj++) {
                    uint32_t b0 = b[nj >> 1][(nj & 1) * 2 + 0];
                    uint32_t b1 = b[nj >> 1][(nj & 1) * 2 + 1];
                    MMA_BF16(acc[mi][nj], a[mi], b0, b1);
                }
        }
    }

    // --- epilogue 1: C . v_x, reduce into logits ---
    const int iBase = (colBase % D) + 32 * warp_n;
    const int kIdx  = colBase / D;              // 256 | 768: boundary clean

    float rs[4][2] = {};
#pragma unroll
    for (int mi = 0; mi < 4; mi++) {
        int r0 = rowBase + 64 * warp_m + 16 * mi + (lane >> 2);
#pragma unroll
        for (int nj = 0; nj < 4; nj++) {
            const float2* v0 = (const float2*)(V + (size_t)r0 * D + iBase
                                               + 8 * nj + 2 * (lane & 3));
            const float2* v1 = (const float2*)(V + (size_t)(r0 + 8) * D + iBase
                                               + 8 * nj + 2 * (lane & 3));
            float2 x0 = *v0, x1 = *v1;
            rs[mi][0] = fmaf(acc[mi][nj][0], x0.x, rs[mi][0]);
            rs[mi][0] = fmaf(acc[mi][nj][1], x0.y, rs[mi][0]);
            rs[mi][1] = fmaf(acc[mi][nj][2], x1.x, rs[mi][1]);
            rs[mi][1] = fmaf(acc[mi][nj][3], x1.y, rs[mi][1]);
        }
    }
#pragma unroll
    for (int mi = 0; mi < 4; mi++)
#pragma unroll
        for (int h = 0; h < 2; h++) {
            rs[mi][h] += __shfl_xor_sync(0xffffffff, rs[mi][h], 1);
            rs[mi][h] += __shfl_xor_sync(0xffffffff, rs[mi][h], 2);
        }
    if ((lane & 3) == 0) {
#pragma unroll
        for (int mi = 0; mi < 4; mi++) {
            int lr = 64 * warp_m + 16 * mi + (lane >> 2);
            atomicAdd(&rowAcc[lr],     rs[mi][0]);
            atomicAdd(&rowAcc[lr + 8], rs[mi][1]);
        }
    }
    __syncthreads();
    if (tid < TM)
        atomicAdd(&g_logits[(rowBase + tid) * 2 + kIdx], rowAcc[tid]);

    // --- device-wide barrier (144 CTAs, 1/SM by smem: all co-resident) ---
    __threadfence();
    __syncthreads();
    if (tid == 0) {
        atomicAdd(&g_sync, 1);
        while (*(volatile int*)&g_sync != NCTA) { }
    }
    __syncthreads();
    __threadfence();

    // --- epilogue 2: softmax(2 logits) + fused combine, strided over grid ---
    const int ctaLin = (blockIdx.z * gridDim.y + blockIdx.y) * gridDim.x + blockIdx.x;
    const int gt = ctaLin * NTHREADS + tid;
    const int stride = NCTA * NTHREADS;         // 73728
#pragma unroll
    for (int i = 0; i < 2; i++) {
        int idx = gt + i * stride;
        if (idx >= B * D / 4) break;
        int b = idx / (D / 4);
        float l0 = g_logits[b * 2 + 0];
        float l1 = g_logits[b * 2 + 1];
        float mx = fmaxf(l0, l1);
        float e0 = expf(l0 - mx);
        float e1 = expf(l1 - mx);
        float inv = 1.0f / (e0 + e1);
        float wa = e0 * inv;
        float wb = e1 * inv;
        float4 v = ((const float4*)V)[idx];
        float4 s = ((const float4*)S)[idx];
        float4 o;
        o.x = wa * v.x + wb * s.x;
        o.y = wa * v.y + wb * s.y;
        o.z = wa * v.z + wb * s.z;
        o.w = wa * v.w + wb * s.w;
        ((float4*)out)[idx] = o;
    }
}

// ---------------------------------------------------------------------------
// Entry point
// ---------------------------------------------------------------------------
extern "C" void kernel_launch(void* const* d_in, const int* in_sizes, int n_in,
                              void* d_out, int out_size) {
    const float* v_x  = (const float*)d_in[0];
    const float* s_x  = (const float*)d_in[1];
    const float* fc_w = (const float*)d_in[2];
    const float* fc_b = (const float*)d_in[3];
    float* out = (float*)d_out;

    cudaFuncSetAttribute(gemm_fuse_kernel,
                         cudaFuncAttributeMaxDynamicSharedMemorySize, SMEM_TOTAL);

    // 1) split + bias init + sync reset
    split_kernel<<<768, 256>>>((const float4*)fc_w, (const float4*)s_x, fc_b);

    // 2) fused HMMA GEMM + dot-reduce + grid barrier + softmax/combine
    dim3 grid(NTOT / TN, B / TM, 6);   // (6, 4, 6) = 144 CTAs
    gemm_fuse_kernel<<<grid, NTHREADS, SMEM_TOTAL>>>(v_x, s_x, out);
}

// round 6
// speedup vs baseline: 1.4286x; 1.4286x over previous
#include <cuda_runtime.h>
#include <cuda_bf16.h>
#include <cstdint>
#include <math.h>

#define D 768
#define B 512
#define NTOT (2 * D)            // 1536 rows of concatenated W

// GEMM tiling: CTA 128x128, 256 threads, warp tile 64x32 (2 x 4 warp grid)
#define TM 128
#define TN 128
#define TK 64                   // bf16 per chunk (128 B = one swizzled row)
#define STAGES 3
#define KHALF 384
#define CHUNKS_PER (KHALF / TK) // 6
#define NCTA 288                // (12, 4, 6)
#define NTHREADS 256

#define A_TILE_BYTES 16384      // 128 x 128B
#define B_TILE_BYTES 16384      // 128 x 128B
#define STAGE_BYTES (A_TILE_BYTES + B_TILE_BYTES)
#define SMEM_TILES_OFF 1024
#define SMEM_TOTAL (SMEM_TILES_OFF + STAGES * STAGE_BYTES)   // 99328

// ---------------------------------------------------------------------------
// Device scratch (allocation-free)
// ---------------------------------------------------------------------------
__device__ __nv_bfloat16 g_s_hi[B * D];
__device__ __nv_bfloat16 g_s_lo[B * D];
__device__ __nv_bfloat16 g_W_hi[NTOT * D];
__device__ __nv_bfloat16 g_W_lo[NTOT * D];
__device__ float g_logits[B * 2];
__device__ int   g_sync;

// ---------------------------------------------------------------------------
// PTX helpers (sm_80-era: legal on the plain sm_103 target)
// ---------------------------------------------------------------------------
__device__ __forceinline__ uint32_t smem_u32(const void* p) {
    uint32_t a;
    asm("{ .reg .u64 t; cvta.to.shared.u64 t, %1; cvt.u32.u64 %0, t; }"
        : "=r"(a) : "l"(p));
    return a;
}

#define SWZ(o) ((o) ^ (((o) >> 3) & 0x70))

__device__ __forceinline__ void cp_async16(uint32_t dst, const void* src) {
    asm volatile("cp.async.cg.shared.global [%0], [%1], 16;"
                 :: "r"(dst), "l"(src));
}
#define CP_COMMIT() asm volatile("cp.async.commit_group;" ::: "memory")
#define CP_WAIT(n)  asm volatile("cp.async.wait_group %0;" :: "n"(n) : "memory")

#define LDSM_X4(r, addr) \
    asm volatile("ldmatrix.sync.aligned.m8n8.x4.shared.b16 {%0,%1,%2,%3}, [%4];" \
                 : "=r"((r)[0]), "=r"((r)[1]), "=r"((r)[2]), "=r"((r)[3]) \
                 : "r"(addr))

#define MMA_BF16(d, a, b0, b1) \
    asm volatile("mma.sync.aligned.m16n8k16.row.col.f32.bf16.bf16.f32 " \
                 "{%0,%1,%2,%3}, {%4,%5,%6,%7}, {%8,%9}, {%0,%1,%2,%3};" \
                 : "+f"((d)[0]), "+f"((d)[1]), "+f"((d)[2]), "+f"((d)[3]) \
                 : "r"((a)[0]), "r"((a)[1]), "r"((a)[2]), "r"((a)[3]), \
                   "r"(b0), "r"(b1))

// ---------------------------------------------------------------------------
// Kernel 1: split fp32 -> bf16 hi/lo; 8 floats/thread, 128-bit stores.
// Also: logits = bias, g_sync = 0.
// ---------------------------------------------------------------------------
__global__ __launch_bounds__(256)
void split_kernel(const float4* __restrict__ W4p,
                  const float4* __restrict__ S4p,
                  const float* __restrict__ fc_b) {
    const int WP = NTOT * D / 8;   // 147456
    const int SP = B * D / 8;      // 49152
    int g = blockIdx.x * blockDim.x + threadIdx.x;

    if (g == 0) g_sync = 0;
    if (g < B * 2) g_logits[g] = fc_b[g & 1];
    if (g >= WP + SP) return;

    float4 x0, x1;
    __nv_bfloat16 *hi, *lo;
    int e;
    if (g < WP) { x0 = W4p[2 * g]; x1 = W4p[2 * g + 1]; hi = g_W_hi; lo = g_W_lo; e = g * 8; }
    else {
        int q = g - WP;
        x0 = S4p[2 * q]; x1 = S4p[2 * q + 1]; hi = g_s_hi; lo = g_s_lo; e = q * 8;
    }

    float v[8] = {x0.x, x0.y, x0.z, x0.w, x1.x, x1.y, x1.z, x1.w};
    uint32_t H[4], L[4];
#pragma unroll
    for (int j = 0; j < 4; j++) {
        float a = v[2 * j], bq = v[2 * j + 1];
        __nv_bfloat162 h2 = __floats2bfloat162_rn(a, bq);
        float ra = a  - __bfloat162float(__low2bfloat16(h2));
        float rb = bq - __bfloat162float(__high2bfloat16(h2));
        __nv_bfloat162 l2 = __floats2bfloat162_rn(ra, rb);
        H[j] = *(uint32_t*)&h2;
        L[j] = *(uint32_t*)&l2;
    }
    *(uint4*)(hi + e) = make_uint4(H[0], H[1], H[2], H[3]);
    *(uint4*)(lo + e) = make_uint4(L[0], L[1], L[2], L[3]);
}

// ---------------------------------------------------------------------------
// Stage loader (256 threads): A tile 128x64 (16 KB) + B tile 128x64 (16 KB),
// 4 rounds each, SW128 swizzle, one commit_group.
// ---------------------------------------------------------------------------
__device__ __forceinline__ void load_stage(uint32_t sA, uint32_t sB,
                                           const __nv_bfloat16* Asrc,
                                           const __nv_bfloat16* Bsrc,
                                           int rowBase, int colBase, int kOff,
                                           int tid) {
#pragma unroll
    for (int r = 0; r < 4; r++) {
        int c = tid + r * NTHREADS;
        int row = c >> 3, col = c & 7;
        uint32_t off = SWZ(row * 128 + col * 16);
        cp_async16(sA + off, Asrc + (size_t)(rowBase + row) * D + kOff + col * 8);
    }
#pragma unroll
    for (int r = 0; r < 4; r++) {
        int c = tid + r * NTHREADS;
        int row = c >> 3, col = c & 7;
        uint32_t off = SWZ(row * 128 + col * 16);
        cp_async16(sB + off, Bsrc + (size_t)(colBase + row) * D + kOff + col * 8);
    }
    CP_COMMIT();
}

// ---------------------------------------------------------------------------
// Kernel 2: HMMA GEMM (warp tile 64x32, 8 warps, 2 CTAs/SM) + v-dot reduce +
// device-wide barrier + softmax/fuse. Grid (12, 4, 6) = 288 CTAs, 256 thr.
// z: seg = z>>1 (hi*hi / hi*lo / lo*hi), khalf = z&1.
// ---------------------------------------------------------------------------
__global__ __launch_bounds__(NTHREADS, 2)
void gemm_fuse_kernel(const float* __restrict__ V,
                      const float* __restrict__ S,
                      float* __restrict__ out) {
    extern __shared__ char smem[];
    const uint32_t smem_base = smem_u32(smem);
    float* rowAcc = (float*)smem;               // 128 floats, below tile area

    const int tid  = threadIdx.x;
    const int wid  = tid >> 5;
    const int lane = tid & 31;
    const int warp_m = wid & 1;                 // 2 x 64 rows
    const int warp_n = wid >> 1;                // 4 x 32 cols

    const int colBase = blockIdx.x * TN;        // 0..1408 within Wcat
    const int rowBase = blockIdx.y * TM;        // 0..384
    const int seg     = blockIdx.z >> 1;        // 0: hi*hi, 1: hi*lo, 2: lo*hi
    const int kOff0   = (blockIdx.z & 1) * KHALF;
    const __nv_bfloat16* Asrc = (seg < 2) ? g_s_hi : g_s_lo;
    const __nv_bfloat16* Bsrc = (seg == 1) ? g_W_lo : g_W_hi;

    if (tid < TM) rowAcc[tid] = 0.0f;

#pragma unroll
    for (int p = 0; p < STAGES - 1; p++) {
        uint32_t sA = smem_base + SMEM_TILES_OFF + p * STAGE_BYTES;
        load_stage(sA, sA + A_TILE_BYTES, Asrc, Bsrc, rowBase, colBase,
                   kOff0 + p * TK, tid);
    }

    float acc[4][4][4] = {};                    // [m16 tile][n8 tile][frag]

    const int rowA = lane & 15, colSelA = lane >> 4;
    const int rowB = ((lane >> 4) << 3) + (lane & 7), colSelB = (lane >> 3) & 1;

    for (int it = 0; it < CHUNKS_PER; it++) {
        if (it < CHUNKS_PER - 1) CP_WAIT(1);
        else                     CP_WAIT(0);
        __syncthreads();

        int nx = it + STAGES - 1;
        if (nx < CHUNKS_PER) {
            uint32_t nA = smem_base + SMEM_TILES_OFF + (nx % STAGES) * STAGE_BYTES;
            load_stage(nA, nA + A_TILE_BYTES, Asrc, Bsrc, rowBase, colBase,
                       kOff0 + nx * TK, tid);
        }

        const uint32_t sA = smem_base + SMEM_TILES_OFF + (it % STAGES) * STAGE_BYTES;
        const uint32_t sB = sA + A_TILE_BYTES;

#pragma unroll
        for (int ks = 0; ks < 4; ks++) {
            uint32_t a[4][4];
            uint32_t b[2][4];
#pragma unroll
            for (int mi = 0; mi < 4; mi++) {
                uint32_t addr = sA + SWZ((64 * warp_m + 16 * mi + rowA) * 128
                                         + (2 * ks + colSelA) * 16);
                LDSM_X4(a[mi], addr);
            }
#pragma unroll
            for (int q = 0; q < 2; q++) {
                uint32_t addr = sB + SWZ((32 * warp_n + 16 * q + rowB) * 128
                                         + (2 * ks + colSelB) * 16);
                LDSM_X4(b[q], addr);
            }
#pragma unroll
            for (int mi = 0; mi < 4; mi++)
#pragma unroll
                for (int nj = 0; nj < 4; nj++) {
                    uint32_t b0 = b[nj >> 1][(nj & 1) * 2 + 0];
                    uint32_t b1 = b[nj >> 1][(nj & 1) * 2 + 1];
                    MMA_BF16(acc[mi][nj], a[mi], b0, b1);
                }
        }
    }

    // --- epilogue 1: C . v_x, reduce into logits ---
    const int iBase = (colBase % D) + 32 * warp_n;
    const int kIdx  = colBase / D;              // 128 | 768: boundary clean

    float rs[4][2] = {};
#pragma unroll
    for (int mi = 0; mi < 4; mi++) {
        int r0 = rowBase + 64 * warp_m + 16 * mi + (lane >> 2);
#pragma unroll
        for (int nj = 0; nj < 4; nj++) {
            const float2* v0 = (const float2*)(V + (size_t)r0 * D + iBase
                                               + 8 * nj + 2 * (lane & 3));
            const float2* v1 = (const float2*)(V + (size_t)(r0 + 8) * D + iBase
                                               + 8 * nj + 2 * (lane & 3));
            float2 x0 = *v0, x1 = *v1;
            rs[mi][0] = fmaf(acc[mi][nj][0], x0.x, rs[mi][0]);
            rs[mi][0] = fmaf(acc[mi][nj][1], x0.y, rs[mi][0]);
            rs[mi][1] = fmaf(acc[mi][nj][2], x1.x, rs[mi][1]);
            rs[mi][1] = fmaf(acc[mi][nj][3], x1.y, rs[mi][1]);
        }
    }
#pragma unroll
    for (int mi = 0; mi < 4; mi++)
#pragma unroll
        for (int h = 0; h < 2; h++) {
            rs[mi][h] += __shfl_xor_sync(0xffffffff, rs[mi][h], 1);
            rs[mi][h] += __shfl_xor_sync(0xffffffff, rs[mi][h], 2);
        }
    if ((lane & 3) == 0) {
#pragma unroll
        for (int mi = 0; mi < 4; mi++) {
            int lr = 64 * warp_m + 16 * mi + (lane >> 2);
            atomicAdd(&rowAcc[lr],     rs[mi][0]);
            atomicAdd(&rowAcc[lr + 8], rs[mi][1]);
        }
    }
    __syncthreads();
    if (tid < TM)
        atomicAdd(&g_logits[(rowBase + tid) * 2 + kIdx], rowAcc[tid]);

    // --- device-wide barrier (288 CTAs, 2/SM co-resident: 288 <= 296) ---
    __threadfence();
    __syncthreads();
    if (tid == 0) {
        atomicAdd(&g_sync, 1);
        while (*(volatile int*)&g_sync != NCTA) { }
    }
    __syncthreads();
    __threadfence();

    // --- epilogue 2: softmax(2 logits) + fused combine, strided over grid ---
    const int ctaLin = (blockIdx.z * gridDim.y + blockIdx.y) * gridDim.x + blockIdx.x;
    const int gt = ctaLin * NTHREADS + tid;
    const int stride = NCTA * NTHREADS;         // 73728
#pragma unroll
    for (int i = 0; i < 2; i++) {
        int idx = gt + i * stride;
        if (idx >= B * D / 4) break;
        int b = idx / (D / 4);
        float l0 = g_logits[b * 2 + 0];
        float l1 = g_logits[b * 2 + 1];
        float mx = fmaxf(l0, l1);
        float e0 = expf(l0 - mx);
        float e1 = expf(l1 - mx);
        float inv = 1.0f / (e0 + e1);
        float wa = e0 * inv;
        float wb = e1 * inv;
        float4 v = ((const float4*)V)[idx];
        float4 s = ((const float4*)S)[idx];
        float4 o;
        o.x = wa * v.x + wb * s.x;
        o.y = wa * v.y + wb * s.y;
        o.z = wa * v.z + wb * s.z;
        o.w = wa * v.w + wb * s.w;
        ((float4*)out)[idx] = o;
    }
}

// ---------------------------------------------------------------------------
// Entry point
// ---------------------------------------------------------------------------
extern "C" void kernel_launch(void* const* d_in, const int* in_sizes, int n_in,
                              void* d_out, int out_size) {
    const float* v_x  = (const float*)d_in[0];
    const float* s_x  = (const float*)d_in[1];
    const float* fc_w = (const float*)d_in[2];
    const float* fc_b = (const float*)d_in[3];
    float* out = (float*)d_out;

    cudaFuncSetAttribute(gemm_fuse_kernel,
                         cudaFuncAttributeMaxDynamicSharedMemorySize, SMEM_TOTAL);

    // 1) split + bias init + sync reset
    split_kernel<<<768, 256>>>((const float4*)fc_w, (const float4*)s_x, fc_b);

    // 2) fused HMMA GEMM + dot-reduce + grid barrier + softmax/combine
    dim3 grid(NTOT / TN, B / TM, 6);   // (12, 4, 6) = 288 CTAs
    gemm_fuse_kernel<<<grid, NTHREADS, SMEM_TOTAL>>>(v_x, s_x, out);
}

// round 7
// speedup vs baseline: 1.5878x; 1.1115x over previous
#include <cuda_runtime.h>
#include <cuda.h>
#include <cuda_bf16.h>
#include <cstdint>
#include <math.h>

#define D 768
#define B 512
#define NTOT (2 * D)            // 1536 rows of concatenated W

// GEMM tiling: CTA 128x128, 256 threads, warp tile 64x32; TK=128 per stage
#define TM 128
#define TN 128
#define TK 128
#define STAGES 3
#define CHUNKS_PER (D / TK)     // 6
#define NCTA 144                // (12, 4, 3)
#define NTHREADS 256

#define STAGE_BYTES 65536       // A 32KB + B 32KB
#define SMEM_MBAR_OFF 640
#define SMEM_TILES_OFF 1024
#define SMEM_TOTAL (SMEM_TILES_OFF + STAGES * STAGE_BYTES)   // 197632

// ---------------------------------------------------------------------------
// Device scratch (allocation-free)
// ---------------------------------------------------------------------------
__device__ __nv_bfloat16 g_s_hi[B * D];
__device__ __nv_bfloat16 g_s_lo[B * D];
__device__ __nv_bfloat16 g_W_hi[NTOT * D];
__device__ __nv_bfloat16 g_W_lo[NTOT * D];
__device__ float g_logits[B * 2];
__device__ int   g_sync;

// ---------------------------------------------------------------------------
// PTX helpers (sm_90 base features only: TMA bulk tensor, mbarrier, ldmatrix,
// mma.sync — all legal on the plain compute_103 target)
// ---------------------------------------------------------------------------
__device__ __forceinline__ uint32_t smem_u32(const void* p) {
    uint32_t a;
    asm("{ .reg .u64 t; cvta.to.shared.u64 t, %1; cvt.u32.u64 %0, t; }"
        : "=r"(a) : "l"(p));
    return a;
}

#define SWZ(o) ((o) ^ (((o) >> 3) & 0x70))

#define MBARRIER_INIT(addr, cnt) \
    asm volatile("mbarrier.init.shared.b64 [%0], %1;" :: "r"(addr), "r"(cnt) : "memory")
#define MBARRIER_EXPECT_TX(addr, bytes) \
    asm volatile("mbarrier.arrive.expect_tx.shared.b64 _, [%0], %1;" \
                 :: "r"(addr), "r"(bytes) : "memory")

__device__ __forceinline__ void mbar_wait(uint32_t mbar, uint32_t parity) {
    uint32_t done;
    asm volatile("{\n\t.reg .pred p;\n\t"
                 "mbarrier.try_wait.parity.acquire.cta.shared::cta.b64 p, [%1], %2;\n\t"
                 "selp.b32 %0, 1, 0, p;\n\t}"
                 : "=r"(done) : "r"(mbar), "r"(parity) : "memory");
    if (!done) {
        asm volatile("{\n\t.reg .pred P1;\n\t"
                     "WL_%=:\n\t"
                     "mbarrier.try_wait.parity.acquire.cta.shared::cta.b64 P1, [%0], %1, 0x989680;\n\t"
                     "@P1 bra.uni WD_%=;\n\t"
                     "bra.uni WL_%=;\n\t"
                     "WD_%=:\n\t}"
                     :: "r"(mbar), "r"(parity) : "memory");
    }
}

__device__ __forceinline__ void tma_load_2d(uint32_t dst, const CUtensorMap* map,
                                            int x, int y, uint32_t mbar) {
    asm volatile("cp.async.bulk.tensor.2d.shared::cta.global.tile.mbarrier::complete_tx::bytes "
                 "[%0], [%1, {%2, %3}], [%4];"
                 :: "r"(dst), "l"(map), "r"(x), "r"(y), "r"(mbar) : "memory");
}

#define LDSM_X4(r, addr) \
    asm volatile("ldmatrix.sync.aligned.m8n8.x4.shared.b16 {%0,%1,%2,%3}, [%4];" \
                 : "=r"((r)[0]), "=r"((r)[1]), "=r"((r)[2]), "=r"((r)[3]) \
                 : "r"(addr))

#define MMA_BF16(d, a, b0, b1) \
    asm volatile("mma.sync.aligned.m16n8k16.row.col.f32.bf16.bf16.f32 " \
                 "{%0,%1,%2,%3}, {%4,%5,%6,%7}, {%8,%9}, {%0,%1,%2,%3};" \
                 : "+f"((d)[0]), "+f"((d)[1]), "+f"((d)[2]), "+f"((d)[3]) \
                 : "r"((a)[0]), "r"((a)[1]), "r"((a)[2]), "r"((a)[3]), \
                   "r"(b0), "r"(b1))

// ---------------------------------------------------------------------------
// Kernel 1: split fp32 -> bf16 hi/lo; 8 floats/thread, 128-bit stores.
// Also: logits = bias, g_sync = 0.
// ---------------------------------------------------------------------------
__global__ __launch_bounds__(256)
void split_kernel(const float4* __restrict__ W4p,
                  const float4* __restrict__ S4p,
                  const float* __restrict__ fc_b) {
    const int WP = NTOT * D / 8;   // 147456
    const int SP = B * D / 8;      // 49152
    int g = blockIdx.x * blockDim.x + threadIdx.x;

    if (g == 0) g_sync = 0;
    if (g < B * 2) g_logits[g] = fc_b[g & 1];
    if (g >= WP + SP) return;

    float4 x0, x1;
    __nv_bfloat16 *hi, *lo;
    int e;
    if (g < WP) { x0 = W4p[2 * g]; x1 = W4p[2 * g + 1]; hi = g_W_hi; lo = g_W_lo; e = g * 8; }
    else {
        int q = g - WP;
        x0 = S4p[2 * q]; x1 = S4p[2 * q + 1]; hi = g_s_hi; lo = g_s_lo; e = q * 8;
    }

    float v[8] = {x0.x, x0.y, x0.z, x0.w, x1.x, x1.y, x1.z, x1.w};
    uint32_t H[4], L[4];
#pragma unroll
    for (int j = 0; j < 4; j++) {
        float a = v[2 * j], bq = v[2 * j + 1];
        __nv_bfloat162 h2 = __floats2bfloat162_rn(a, bq);
        float ra = a  - __bfloat162float(__low2bfloat16(h2));
        float rb = bq - __bfloat162float(__high2bfloat16(h2));
        __nv_bfloat162 l2 = __floats2bfloat162_rn(ra, rb);
        H[j] = *(uint32_t*)&h2;
        L[j] = *(uint32_t*)&l2;
    }
    *(uint4*)(hi + e) = make_uint4(H[0], H[1], H[2], H[3]);
    *(uint4*)(lo + e) = make_uint4(L[0], L[1], L[2], L[3]);
}

// ---------------------------------------------------------------------------
// Kernel 2: TMA-fed HMMA GEMM (warp tile 64x32, 8 warps, 1 CTA/SM) +
// v-dot reduce + device-wide barrier + softmax/fuse.
// Grid (12, 4, 3) = 144 CTAs, 256 threads. z = split term.
// Stage = A[128 rows x 128 cols bf16] + B[...], loaded as 4 TMA boxes
// of 64 cols x 128 rows each (SW128-swizzled, matching LDSM addressing).
// ---------------------------------------------------------------------------
__global__ __launch_bounds__(NTHREADS, 1)
void gemm_fuse_kernel(const float* __restrict__ V,
                      const float* __restrict__ S,
                      float* __restrict__ out,
                      const __grid_constant__ CUtensorMap map_shi,
                      const __grid_constant__ CUtensorMap map_slo,
                      const __grid_constant__ CUtensorMap map_whi,
                      const __grid_constant__ CUtensorMap map_wlo) {
    extern __shared__ __align__(1024) char smem[];
    const uint32_t smem_base = smem_u32(smem);
    float* rowAcc = (float*)smem;               // 128 floats at offset 0

    const int tid  = threadIdx.x;
    const int wid  = tid >> 5;
    const int lane = tid & 31;
    const int warp_m = wid & 1;                 // 2 x 64 rows
    const int warp_n = wid >> 1;                // 4 x 32 cols

    const int colBase = blockIdx.x * TN;        // 0..1408 within Wcat
    const int rowBase = blockIdx.y * TM;        // 0..384
    const int seg     = blockIdx.z;             // 0: hi*hi, 1: hi*lo, 2: lo*hi
    const CUtensorMap* mA = (seg < 2) ? &map_shi : &map_slo;
    const CUtensorMap* mB = (seg == 1) ? &map_wlo : &map_whi;

    if (tid < TM) rowAcc[tid] = 0.0f;
    if (tid < STAGES) MBARRIER_INIT(smem_base + SMEM_MBAR_OFF + tid * 8, 1);
    __syncthreads();

    // prologue: issue stages 0, 1
    if (tid == 0) {
#pragma unroll
        for (int p = 0; p < STAGES - 1; p++) {
            uint32_t mb  = smem_base + SMEM_MBAR_OFF + p * 8;
            uint32_t dst = smem_base + SMEM_TILES_OFF + p * STAGE_BYTES;
            MBARRIER_EXPECT_TX(mb, STAGE_BYTES);
            int k = p * TK;
            tma_load_2d(dst,         mA, k,      rowBase, mb);
            tma_load_2d(dst + 16384, mA, k + 64, rowBase, mb);
            tma_load_2d(dst + 32768, mB, k,      colBase, mb);
            tma_load_2d(dst + 49152, mB, k + 64, colBase, mb);
        }
    }

    float acc[4][4][4] = {};                    // [m16 tile][n8 tile][frag]

    const int rowA = lane & 15, colSelA = lane >> 4;
    const int rowB = ((lane >> 4) << 3) + (lane & 7), colSelB = (lane >> 3) & 1;

    for (int it = 0; it < CHUNKS_PER; it++) {
        // issue chunk it+2 (its buffer was consumed at it-1, synced below)
        int nx = it + STAGES - 1;
        if (tid == 0 && nx < CHUNKS_PER) {
            int s = nx % STAGES;
            uint32_t mb  = smem_base + SMEM_MBAR_OFF + s * 8;
            uint32_t dst = smem_base + SMEM_TILES_OFF + s * STAGE_BYTES;
            MBARRIER_EXPECT_TX(mb, STAGE_BYTES);
            int k = nx * TK;
            tma_load_2d(dst,         mA, k,      rowBase, mb);
            tma_load_2d(dst + 16384, mA, k + 64, rowBase, mb);
            tma_load_2d(dst + 32768, mB, k,      colBase, mb);
            tma_load_2d(dst + 49152, mB, k + 64, colBase, mb);
        }

        mbar_wait(smem_base + SMEM_MBAR_OFF + (it % STAGES) * 8,
                  (uint32_t)((it / STAGES) & 1));

        const uint32_t sA = smem_base + SMEM_TILES_OFF + (it % STAGES) * STAGE_BYTES;
        const uint32_t sB = sA + 32768;

#pragma unroll
        for (int ks = 0; ks < 8; ks++) {
            const uint32_t blk = (uint32_t)(ks >> 2) * 16384;
            const int c2 = ks & 3;
            uint32_t a[4][4];
            uint32_t b[2][4];
#pragma unroll
            for (int mi = 0; mi < 4; mi++) {
                uint32_t addr = sA + blk + SWZ((64 * warp_m + 16 * mi + rowA) * 128
                                               + (2 * c2 + colSelA) * 16);
                LDSM_X4(a[mi], addr);
            }
#pragma unroll
            for (int q = 0; q < 2; q++) {
                uint32_t addr = sB + blk + SWZ((32 * warp_n + 16 * q + rowB) * 128
                                               + (2 * c2 + colSelB) * 16);
                LDSM_X4(b[q], addr);
            }
#pragma unroll
            for (int mi = 0; mi < 4; mi++)
#pragma unroll
                for (int nj = 0; nj < 4; nj++) {
                    uint32_t b0 = b[nj >> 1][(nj & 1) * 2 + 0];
                    uint32_t b1 = b[nj >> 1][(nj & 1) * 2 + 1];
                    MMA_BF16(acc[mi][nj], a[mi], b0, b1);
                }
        }
        __syncthreads();   // all warps done reading buffer (it%3) -> reusable
    }

    // --- epilogue 1: C . v_x, reduce into logits ---
    const int iBase = (colBase % D) + 32 * warp_n;
    const int kIdx  = colBase / D;

    float rs[4][2] = {};
#pragma unroll
    for (int mi = 0; mi < 4; mi++) {
        int r0 = rowBase + 64 * warp_m + 16 * mi + (lane >> 2);
#pragma unroll
        for (int nj = 0; nj < 4; nj++) {
            const float2* v0 = (const float2*)(V + (size_t)r0 * D + iBase
                                               + 8 * nj + 2 * (lane & 3));
            const float2* v1 = (const float2*)(V + (size_t)(r0 + 8) * D + iBase
                                               + 8 * nj + 2 * (lane & 3));
            float2 x0 = *v0, x1 = *v1;
            rs[mi][0] = fmaf(acc[mi][nj][0], x0.x, rs[mi][0]);
            rs[mi][0] = fmaf(acc[mi][nj][1], x0.y, rs[mi][0]);
            rs[mi][1] = fmaf(acc[mi][nj][2], x1.x, rs[mi][1]);
            rs[mi][1] = fmaf(acc[mi][nj][3], x1.y, rs[mi][1]);
        }
    }
#pragma unroll
    for (int mi = 0; mi < 4; mi++)
#pragma unroll
        for (int h = 0; h < 2; h++) {
            rs[mi][h] += __shfl_xor_sync(0xffffffff, rs[mi][h], 1);
            rs[mi][h] += __shfl_xor_sync(0xffffffff, rs[mi][h], 2);
        }
    if ((lane & 3) == 0) {
#pragma unroll
        for (int mi = 0; mi < 4; mi++) {
            int lr = 64 * warp_m + 16 * mi + (lane >> 2);
            atomicAdd(&rowAcc[lr],     rs[mi][0]);
            atomicAdd(&rowAcc[lr + 8], rs[mi][1]);
        }
    }
    __syncthreads();
    if (tid < TM)
        atomicAdd(&g_logits[(rowBase + tid) * 2 + kIdx], rowAcc[tid]);

    // --- device-wide barrier (144 CTAs, 1/SM by smem: all co-resident) ---
    __threadfence();
    __syncthreads();
    if (tid == 0) {
        atomicAdd(&g_sync, 1);
        while (*(volatile int*)&g_sync != NCTA) { }
    }
    __syncthreads();
    __threadfence();

    // --- epilogue 2: softmax(2 logits) + fused combine, strided over grid ---
    const int ctaLin = (blockIdx.z * gridDim.y + blockIdx.y) * gridDim.x + blockIdx.x;
    const int gt = ctaLin * NTHREADS + tid;
    const int stride = NCTA * NTHREADS;         // 36864
#pragma unroll
    for (int i = 0; i < 3; i++) {
        int idx = gt + i * stride;
        if (idx >= B * D / 4) break;
        int b = idx / (D / 4);
        float l0 = g_logits[b * 2 + 0];
        float l1 = g_logits[b * 2 + 1];
        float mx = fmaxf(l0, l1);
        float e0 = expf(l0 - mx);
        float e1 = expf(l1 - mx);
        float inv = 1.0f / (e0 + e1);
        float wa = e0 * inv;
        float wb = e1 * inv;
        float4 v = ((const float4*)V)[idx];
        float4 s = ((const float4*)S)[idx];
        float4 o;
        o.x = wa * v.x + wb * s.x;
        o.y = wa * v.y + wb * s.y;
        o.z = wa * v.z + wb * s.z;
        o.w = wa * v.w + wb * s.w;
        ((float4*)out)[idx] = o;
    }
}

// ---------------------------------------------------------------------------
// Host: tensormap construction via driver entry point (no -lcuda needed)
// ---------------------------------------------------------------------------
typedef CUresult (*PFN_encodeTiled)(
    CUtensorMap*, CUtensorMapDataType, cuuint32_t, void*,
    const cuuint64_t*, const cuuint64_t*, const cuuint32_t*, const cuuint32_t*,
    CUtensorMapInterleave, CUtensorMapSwizzle, CUtensorMapL2promotion,
    CUtensorMapFloatOOBfill);

static void make_map(PFN_encodeTiled fn, CUtensorMap* m, void* base,
                     unsigned long long rows, unsigned int boxRows) {
    cuuint64_t gd[2] = {(cuuint64_t)D, (cuuint64_t)rows};
    cuuint64_t gs[1] = {(cuuint64_t)(D * 2)};     // row stride in bytes
    cuuint32_t bd[2] = {64u, boxRows};            // 64 bf16 = 128 B inner box
    cuuint32_t es[2] = {1u, 1u};
    fn(m, CU_TENSOR_MAP_DATA_TYPE_BFLOAT16, 2, base, gd, gs, bd, es,
       CU_TENSOR_MAP_INTERLEAVE_NONE, CU_TENSOR_MAP_SWIZZLE_128B,
       CU_TENSOR_MAP_L2_PROMOTION_L2_128B, CU_TENSOR_MAP_FLOAT_OOB_FILL_NONE);
}

extern "C" void kernel_launch(void* const* d_in, const int* in_sizes, int n_in,
                              void* d_out, int out_size) {
    const float* v_x  = (const float*)d_in[0];
    const float* s_x  = (const float*)d_in[1];
    const float* fc_w = (const float*)d_in[2];
    const float* fc_b = (const float*)d_in[3];
    float* out = (float*)d_out;

    cudaFuncSetAttribute(gemm_fuse_kernel,
                         cudaFuncAttributeMaxDynamicSharedMemorySize, SMEM_TOTAL);

    // Resolve cuTensorMapEncodeTiled through the runtime (graph-capture safe:
    // host-side only, no stream ops, no allocation).
    PFN_encodeTiled encode = nullptr;
    cudaDriverEntryPointQueryResult qres;
    cudaGetDriverEntryPoint("cuTensorMapEncodeTiled", (void**)&encode,
                            cudaEnableDefault, &qres);

    void *p_shi, *p_slo, *p_whi, *p_wlo;
    cudaGetSymbolAddress(&p_shi, g_s_hi);
    cudaGetSymbolAddress(&p_slo, g_s_lo);
    cudaGetSymbolAddress(&p_whi, g_W_hi);
    cudaGetSymbolAddress(&p_wlo, g_W_lo);

    CUtensorMap m_shi, m_slo, m_whi, m_wlo;
    make_map(encode, &m_shi, p_shi, B,    TM);
    make_map(encode, &m_slo, p_slo, B,    TM);
    make_map(encode, &m_whi, p_whi, NTOT, TN);
    make_map(encode, &m_wlo, p_wlo, NTOT, TN);

    // 1) split + bias init + sync reset
    split_kernel<<<768, 256>>>((const float4*)fc_w, (const float4*)s_x, fc_b);

    // 2) TMA-fed HMMA GEMM + dot-reduce + grid barrier + softmax/combine
    dim3 grid(NTOT / TN, B / TM, 3);   // (12, 4, 3) = 144 CTAs
    gemm_fuse_kernel<<<grid, NTHREADS, SMEM_TOTAL>>>(v_x, s_x, out,
                                                     m_shi, m_slo, m_whi, m_wlo);
}